// round 14
// baseline (speedup 1.0000x reference)
#include <cuda_runtime.h>
#include <cuda_fp16.h>
#include <cstdint>

#define N_NODES_C  100000
#define N_EDGES_C  1600000
#define CH         128
#define N_GRAPHS_C 256
#define NBLK       ((N_NODES_C + 255) / 256)   // 391
#define SXP        136                          // padded smem X row stride (halves)
#define E2GRID     ((N_EDGES_C / 2 + 255) / 256)  // 3125
#define GGRID      ((N_NODES_C + 127) / 128)      // 782

// ---------------- scratch (static device globals; zero-initialized at load) ----------------
__device__ __half g_bufA[(size_t)N_NODES_C * CH];  // 25.6 MB (Hs, fp16)
__device__ __half g_bufB[(size_t)N_NODES_C * CH];  // 25.6 MB (h1, fp16)
__device__ float g_dis[N_NODES_C];                 // deg^-0.5
__device__ int   g_cnt[N_NODES_C];                 // in-degree histogram (reset by scan kernel)
__device__ int   g_rowptr[N_NODES_C + 1];
__device__ int   g_cursor[N_NODES_C];
__device__ int   g_csr_src[N_EDGES_C];
__device__ unsigned long long g_scan_state[512];   // (flag<<32)|sum (reset by fused csr path)
__device__ float g_gsum[N_GRAPHS_C];               // reset by final_out
__device__ float g_gcnt[N_GRAPHS_C];               // reset by final_out
__device__ uint32_t g_W1p[8192];                   // fragment-packed fp16 W1 (32 KB)
__device__ uint32_t g_W2p[8192];                   // fragment-packed fp16 W2 (32 KB)

// bit-cast __half2 -> uint32_t (register no-op)
__device__ __forceinline__ uint32_t h2u(__half2 h) {
    union { __half2 h; uint32_t u; } c;
    c.h = h;
    return c.u;
}

// ---------------- fused: W prepack (block 0) + degree/graph count (blocks 1..E2GRID) ----------------
__global__ __launch_bounds__(256) void prepack_cnt_kernel(
    const float* __restrict__ W1, const float* __restrict__ W2,
    const int* __restrict__ dst, const int* __restrict__ batch)
{
    int tid = threadIdx.x;
    if (blockIdx.x == 0) {
        // W prepack: idx = (kk*16+nt)*64 + lane*2 + r
        // k = kk*16 + r*8 + (lane&3)*2 ; n = nt*8 + (lane>>2)
        #pragma unroll
        for (int v = 0; v < 32; v++) {
            int idx   = tid + v * 256;
            int r     = idx & 1;
            int lane_ = (idx >> 1) & 31;
            int nt    = (idx >> 6) & 15;
            int kk    = idx >> 10;
            int k = kk * 16 + r * 8 + (lane_ & 3) * 2;
            int n = nt * 8 + (lane_ >> 2);
            size_t o0 = (size_t)k * CH + n;
            size_t o1 = (size_t)(k + 1) * CH + n;
            g_W1p[idx] = h2u(__floats2half2_rn(__ldg(W1 + o0), __ldg(W1 + o1)));
            g_W2p[idx] = h2u(__floats2half2_rn(__ldg(W2 + o0), __ldg(W2 + o1)));
        }
    } else {
        int i = (blockIdx.x - 1) * 256 + tid;
        if (i * 2 + 1 < N_EDGES_C) {
            int2 d = *(const int2*)(dst + i * 2);
            atomicAdd(&g_cnt[d.x], 1);
            atomicAdd(&g_cnt[d.y], 1);
        } else if (i * 2 < N_EDGES_C) {
            atomicAdd(&g_cnt[dst[i * 2]], 1);
        }
        if (i < N_NODES_C) atomicAdd(&g_gcnt[batch[i]], 1.0f);
    }
}

// ---------------- single-pass decoupled-lookback scan + rowptr/cursor/dis + cnt reset ----------------
__global__ __launch_bounds__(256) void scan_lookback_kernel() {
    __shared__ int s[256];
    __shared__ int sP;
    const int b = blockIdx.x;
    const int t = threadIdx.x;
    const int i = b * 256 + t;

    int c = (i < N_NODES_C) ? g_cnt[i] : 0;
    s[t] = c;
    __syncthreads();
    for (int o = 1; o < 256; o <<= 1) {
        int u = (t >= o) ? s[t - o] : 0;
        __syncthreads();
        s[t] += u;
        __syncthreads();
    }
    const int total = s[255];

    if (b == 0) {
        if (t == 0) {
            atomicExch(&g_scan_state[0], (2ull << 32) | (unsigned)total);
            sP = 0;
        }
    } else {
        if (t == 0)
            atomicExch(&g_scan_state[b], (1ull << 32) | (unsigned)total);
        if (t < 32) {
            int lane = t;
            int P = 0;
            int j = b - 1;
            while (true) {
                int idx = j - lane;
                int flag = 0, val = 0;
                if (idx >= 0) {
                    unsigned long long v;
                    do { v = atomicAdd(&g_scan_state[idx], 0ull); flag = (int)(v >> 32); }
                    while (flag == 0);
                    val = (int)(v & 0xffffffffu);
                }
                unsigned m = __ballot_sync(0xFFFFFFFFu, (idx >= 0) && (flag == 2));
                if (m) {
                    int firstP = __ffs(m) - 1;
                    int contrib = (lane <= firstP) ? val : 0;
                    P += __reduce_add_sync(0xFFFFFFFFu, contrib);
                    break;
                } else {
                    P += __reduce_add_sync(0xFFFFFFFFu, (idx >= 0) ? val : 0);
                    j -= 32;
                }
            }
            if (lane == 0) {
                atomicExch(&g_scan_state[b], (2ull << 32) | (unsigned)(P + total));
                sP = P;
            }
        }
    }
    __syncthreads();

    if (i < N_NODES_C) {
        int pos = sP + s[t] - c;
        g_rowptr[i] = pos;
        g_cursor[i] = pos;
        g_dis[i]    = rsqrtf(1.0f + (float)c);
        g_cnt[i]    = 0;
    }
    if (b == 0 && t == 0) g_rowptr[N_NODES_C] = N_EDGES_C;
}

// ---------------- fused: GEMM layer-1 (blocks 0..GGRID) + CSR fill (blocks GGRID..) ----------------
// GEMM: Y[r,:] = half((X[r,:] @ W) * scale[r]) via m16n8k16, X fp32.
// CSR: g_csr_src[cursor[dst]++] = src ; also resets scan_state.
__global__ __launch_bounds__(256) void gemm1_csr_kernel(
    const float* __restrict__ X, const uint32_t* __restrict__ Wp,
    __half* __restrict__ Y, const float* __restrict__ scale,
    const int* __restrict__ src, const int* __restrict__ dst)
{
    __shared__ __half sX[128 * SXP];         // 34816 B (unused by csr blocks)

    const int tid = threadIdx.x;

    if (blockIdx.x >= GGRID) {
        // ---- CSR fill path ----
        int i = (blockIdx.x - GGRID) * 256 + tid;
        if (i < 512) g_scan_state[i] = 0ull;
        if (i * 2 + 1 < N_EDGES_C) {
            int2 s = *(const int2*)(src + i * 2);
            int2 d = *(const int2*)(dst + i * 2);
            g_csr_src[atomicAdd(&g_cursor[d.x], 1)] = s.x;
            g_csr_src[atomicAdd(&g_cursor[d.y], 1)] = s.y;
        } else if (i * 2 < N_EDGES_C) {
            g_csr_src[atomicAdd(&g_cursor[dst[i * 2]], 1)] = src[i * 2];
        }
        return;
    }

    // ---- GEMM path ----
    const int warp = tid >> 5;
    const int lane = tid & 31;
    const int gid  = lane >> 2;
    const int tig  = lane & 3;
    const int rowBase = blockIdx.x * 128;
    const int M = N_NODES_C;

    #pragma unroll
    for (int v = 0; v < 16; v++) {
        int fi = tid + v * 256;              // 4096 float4
        int r  = fi >> 5;
        int c4 = (fi & 31) * 4;
        float4 val = make_float4(0.f, 0.f, 0.f, 0.f);
        int gr = rowBase + r;
        if (gr < M) val = *(const float4*)(X + (size_t)gr * CH + c4);
        uint32_t* p = (uint32_t*)(sX + r * SXP + c4);
        p[0] = h2u(__floats2half2_rn(val.x, val.y));
        p[1] = h2u(__floats2half2_rn(val.z, val.w));
    }
    __syncthreads();

    float acc[16][4];
    #pragma unroll
    for (int nt = 0; nt < 16; nt++)
        #pragma unroll
        for (int j = 0; j < 4; j++) acc[nt][j] = 0.f;

    const int arow = warp * 16 + gid;

    #pragma unroll
    for (int kk = 0; kk < 8; kk++) {
        uint32_t a0 = *(const uint32_t*)(sX + arow * SXP       + kk * 16 + tig * 2);
        uint32_t a1 = *(const uint32_t*)(sX + (arow + 8) * SXP + kk * 16 + tig * 2);
        uint32_t a2 = *(const uint32_t*)(sX + arow * SXP       + kk * 16 + tig * 2 + 8);
        uint32_t a3 = *(const uint32_t*)(sX + (arow + 8) * SXP + kk * 16 + tig * 2 + 8);
        #pragma unroll
        for (int nt = 0; nt < 16; nt++) {
            uint2 b = *(const uint2*)(Wp + (size_t)(kk * 16 + nt) * 64 + lane * 2);
            float* c = acc[nt];
            asm volatile(
                "mma.sync.aligned.m16n8k16.row.col.f32.f16.f16.f32 "
                "{%0,%1,%2,%3}, {%4,%5,%6,%7}, {%8,%9}, {%0,%1,%2,%3};"
                : "+f"(c[0]), "+f"(c[1]), "+f"(c[2]), "+f"(c[3])
                : "r"(a0), "r"(a1), "r"(a2), "r"(a3), "r"(b.x), "r"(b.y));
        }
    }

    const int r0 = rowBase + warp * 16 + gid;
    const int r1 = r0 + 8;
    const bool v0 = (r0 < M);
    const bool v1 = (r1 < M);
    float s0 = v0 ? scale[r0] : 0.f;
    float s1 = v1 ? scale[r1] : 0.f;
    #pragma unroll
    for (int nt = 0; nt < 16; nt++) {
        int col = nt * 8 + tig * 2;
        if (v0)
            *(__half2*)(Y + (size_t)r0 * CH + col) =
                __floats2half2_rn(acc[nt][0] * s0, acc[nt][1] * s0);
        if (v1)
            *(__half2*)(Y + (size_t)r1 * CH + col) =
                __floats2half2_rn(acc[nt][2] * s1, acc[nt][3] * s1);
    }
}

// ---------------- standalone fp16-input GEMM (layer 2) ----------------
__global__ __launch_bounds__(256) void gemm_f16_kernel(
    const __half* __restrict__ X, const uint32_t* __restrict__ Wp,
    __half* __restrict__ Y, const float* __restrict__ scale, int M)
{
    __shared__ __half sX[128 * SXP];

    const int tid  = threadIdx.x;
    const int warp = tid >> 5;
    const int lane = tid & 31;
    const int gid  = lane >> 2;
    const int tig  = lane & 3;
    const int rowBase = blockIdx.x * 128;

    #pragma unroll
    for (int v = 0; v < 8; v++) {
        int fi = tid + v * 256;              // 2048 uint4
        int r  = fi >> 4;
        int c8 = (fi & 15) * 8;
        uint4 val = make_uint4(0u, 0u, 0u, 0u);
        int gr = rowBase + r;
        if (gr < M) val = *(const uint4*)(X + (size_t)gr * CH + c8);
        uint32_t* p = (uint32_t*)(sX + r * SXP + c8);
        p[0] = val.x; p[1] = val.y; p[2] = val.z; p[3] = val.w;
    }
    __syncthreads();

    float acc[16][4];
    #pragma unroll
    for (int nt = 0; nt < 16; nt++)
        #pragma unroll
        for (int j = 0; j < 4; j++) acc[nt][j] = 0.f;

    const int arow = warp * 16 + gid;

    #pragma unroll
    for (int kk = 0; kk < 8; kk++) {
        uint32_t a0 = *(const uint32_t*)(sX + arow * SXP       + kk * 16 + tig * 2);
        uint32_t a1 = *(const uint32_t*)(sX + (arow + 8) * SXP + kk * 16 + tig * 2);
        uint32_t a2 = *(const uint32_t*)(sX + arow * SXP       + kk * 16 + tig * 2 + 8);
        uint32_t a3 = *(const uint32_t*)(sX + (arow + 8) * SXP + kk * 16 + tig * 2 + 8);
        #pragma unroll
        for (int nt = 0; nt < 16; nt++) {
            uint2 b = *(const uint2*)(Wp + (size_t)(kk * 16 + nt) * 64 + lane * 2);
            float* c = acc[nt];
            asm volatile(
                "mma.sync.aligned.m16n8k16.row.col.f32.f16.f16.f32 "
                "{%0,%1,%2,%3}, {%4,%5,%6,%7}, {%8,%9}, {%0,%1,%2,%3};"
                : "+f"(c[0]), "+f"(c[1]), "+f"(c[2]), "+f"(c[3])
                : "r"(a0), "r"(a1), "r"(a2), "r"(a3), "r"(b.x), "r"(b.y));
        }
    }

    const int r0 = rowBase + warp * 16 + gid;
    const int r1 = r0 + 8;
    const bool v0 = (r0 < M);
    const bool v1 = (r1 < M);
    float s0 = v0 ? scale[r0] : 0.f;
    float s1 = v1 ? scale[r1] : 0.f;
    #pragma unroll
    for (int nt = 0; nt < 16; nt++) {
        int col = nt * 8 + tig * 2;
        if (v0)
            *(__half2*)(Y + (size_t)r0 * CH + col) =
                __floats2half2_rn(acc[nt][0] * s0, acc[nt][1] * s0);
        if (v1)
            *(__half2*)(Y + (size_t)r1 * CH + col) =
                __floats2half2_rn(acc[nt][2] * s1, acc[nt][3] * s1);
    }
}

// ---------------- gather aggregation (fp16 Hs rows pre-scaled by dis[row]) ----------------
__device__ __forceinline__ void acc_row(float4& acc, const __half* Hs, int srow, int lane) {
    uint2 raw = *(const uint2*)(Hs + (size_t)srow * CH + lane * 4);
    float2 f0 = __half22float2(*(__half2*)&raw.x);
    float2 f1 = __half22float2(*(__half2*)&raw.y);
    acc.x += f0.x; acc.y += f0.y; acc.z += f1.x; acc.w += f1.y;
}

template <int MODE>
__global__ __launch_bounds__(256) void agg_kernel(
    const __half* __restrict__ Hs, const float* __restrict__ bias,
    __half* __restrict__ OUT,
    const float* __restrict__ Wfc, const int* __restrict__ batch)
{
    int node = (blockIdx.x * blockDim.x + threadIdx.x) >> 5;
    int lane = threadIdx.x & 31;
    if (node >= N_NODES_C) return;

    float4 acc = make_float4(0.f, 0.f, 0.f, 0.f);
    acc_row(acc, Hs, node, lane);            // self term

    int beg = __ldg(&g_rowptr[node]);
    int end = __ldg(&g_rowptr[node + 1]);

    for (int j = beg; j < end; j += 32) {
        int n = min(32, end - j);
        int si = (lane < n) ? __ldg(&g_csr_src[j + lane]) : 0;
        int t = 0;
        for (; t + 8 <= n; t += 8) {
            int ss[8];
            #pragma unroll
            for (int k = 0; k < 8; k++) ss[k] = __shfl_sync(0xFFFFFFFFu, si, t + k);
            #pragma unroll
            for (int k = 0; k < 8; k++) acc_row(acc, Hs, ss[k], lane);
        }
        for (; t + 2 <= n; t += 2) {
            int s0 = __shfl_sync(0xFFFFFFFFu, si, t);
            int s1 = __shfl_sync(0xFFFFFFFFu, si, t + 1);
            acc_row(acc, Hs, s0, lane);
            acc_row(acc, Hs, s1, lane);
        }
        if (t < n) {
            int s0 = __shfl_sync(0xFFFFFFFFu, si, t);
            acc_row(acc, Hs, s0, lane);
        }
    }

    float dd = __ldg(&g_dis[node]);
    float4 b4 = *(const float4*)(bias + lane * 4);
    acc.x = fmaxf(acc.x * dd + b4.x, 0.f);
    acc.y = fmaxf(acc.y * dd + b4.y, 0.f);
    acc.z = fmaxf(acc.z * dd + b4.z, 0.f);
    acc.w = fmaxf(acc.w * dd + b4.w, 0.f);

    if (MODE == 0) {
        uint2 o;
        o.x = h2u(__floats2half2_rn(acc.x, acc.y));
        o.y = h2u(__floats2half2_rn(acc.z, acc.w));
        *(uint2*)(OUT + (size_t)node * CH + lane * 4) = o;
    } else {
        float4 w4 = *(const float4*)(Wfc + lane * 4);
        float s = acc.x * w4.x + acc.y * w4.y + acc.z * w4.z + acc.w * w4.w;
        #pragma unroll
        for (int o = 16; o; o >>= 1) s += __shfl_xor_sync(0xFFFFFFFFu, s, o);
        if (lane == 0) atomicAdd(&g_gsum[__ldg(batch + node)], s);
    }
}

// ---------------- final output (+ pool-state reset) ----------------
__global__ void final_out_kernel(float* __restrict__ out, const float* __restrict__ bfc) {
    int g = threadIdx.x;
    if (g < N_GRAPHS_C) {
        out[g] = g_gsum[g] / fmaxf(g_gcnt[g], 1.0f) + bfc[0];
        g_gsum[g] = 0.f;
        g_gcnt[g] = 0.f;
    }
}

// ---------------- launch (7 kernels, plain launches only) ----------------
extern "C" void kernel_launch(void* const* d_in, const int* in_sizes, int n_in,
                              void* d_out, int out_size)
{
    const float* x    = (const float*)d_in[0];
    const int*   edge = (const int*)  d_in[1];
    const int*   batch= (const int*)  d_in[2];
    const float* W1   = (const float*)d_in[3];
    const float* b1   = (const float*)d_in[4];
    const float* W2   = (const float*)d_in[5];
    const float* b2   = (const float*)d_in[6];
    const float* Wfc  = (const float*)d_in[7];
    const float* bfc  = (const float*)d_in[8];
    float* out = (float*)d_out;

    const int* srcp = edge;
    const int* dstp = edge + N_EDGES_C;

    __half *bufA = nullptr, *bufB = nullptr;
    float *disp = nullptr;
    uint32_t *w1p = nullptr, *w2p = nullptr;
    cudaGetSymbolAddress((void**)&bufA, g_bufA);
    cudaGetSymbolAddress((void**)&bufB, g_bufB);
    cudaGetSymbolAddress((void**)&disp, g_dis);
    cudaGetSymbolAddress((void**)&w1p, g_W1p);
    cudaGetSymbolAddress((void**)&w2p, g_W2p);

    const int agrid = (N_NODES_C + 7) / 8;

    // ---- fused prepack + degree/graph count ----
    prepack_cnt_kernel<<<E2GRID + 1, 256>>>(W1, W2, dstp, batch);

    // ---- scan: rowptr/cursor/dis ----
    scan_lookback_kernel<<<NBLK, 256>>>();

    // ---- fused layer-1 GEMM + CSR fill (independent; overlap) ----
    gemm1_csr_kernel<<<GGRID + E2GRID, 256>>>(x, w1p, bufA, disp, srcp, dstp);

    // ---- layer 1 aggregation ----
    agg_kernel<0><<<agrid, 256>>>(bufA, b1, bufB, nullptr, nullptr);

    // ---- layer 2 ----
    gemm_f16_kernel<<<GGRID, 256>>>(bufB, w2p, bufA, disp, N_NODES_C);
    agg_kernel<1><<<agrid, 256>>>(bufA, b2, nullptr, Wfc, batch);

    // ---- final (+ reset pooling state) ----
    final_out_kernel<<<1, 256>>>(out, bfc);

    (void)in_sizes; (void)n_in; (void)out_size;
}

// round 16
// speedup vs baseline: 1.0525x; 1.0525x over previous
#include <cuda_runtime.h>
#include <cuda_fp16.h>
#include <cstdint>

#define N_NODES_C  100000
#define N_EDGES_C  1600000
#define CH         128
#define N_GRAPHS_C 256
#define NBLK       ((N_NODES_C + 255) / 256)   // 391
#define SXP        136                          // padded smem X row stride (halves)
#define E2GRID     ((N_EDGES_C / 2 + 255) / 256)  // 3125
#define GGRID      ((N_NODES_C + 127) / 128)      // 782

// ---------------- scratch (static device globals; zero-initialized at load) ----------------
__device__ __half g_bufA[(size_t)N_NODES_C * CH];  // 25.6 MB (Hs, fp16)
__device__ __half g_bufB[(size_t)N_NODES_C * CH];  // 25.6 MB (h1, fp16)
__device__ float g_dis[N_NODES_C];                 // deg^-0.5
__device__ int   g_cnt[N_NODES_C];                 // in-degree histogram (reset by scan kernel)
__device__ int   g_rowptr[N_NODES_C + 1];
__device__ int   g_cursor[N_NODES_C];
__device__ int   g_csr_src[N_EDGES_C];
__device__ unsigned long long g_scan_state[512];   // (flag<<32)|sum (reset by csr_fill)
__device__ float g_gsum[N_GRAPHS_C];               // reset by final_out
__device__ float g_gcnt[N_GRAPHS_C];               // reset by final_out
__device__ uint32_t g_W1p[8192];                   // fragment-packed fp16 W1 (32 KB)
__device__ uint32_t g_W2p[8192];                   // fragment-packed fp16 W2 (32 KB)

// bit-casts (register no-ops)
__device__ __forceinline__ uint32_t h2u(__half2 h) {
    union { __half2 h; uint32_t u; } c; c.h = h; return c.u;
}
__device__ __forceinline__ __half2 u2h(uint32_t u) {
    union { uint32_t u; __half2 h; } c; c.u = u; return c.h;
}

// ---------------- fused: W prepack (block 0) + degree/graph count (blocks 1..E2GRID) ----------------
__global__ __launch_bounds__(256) void prepack_cnt_kernel(
    const float* __restrict__ W1, const float* __restrict__ W2,
    const int* __restrict__ dst, const int* __restrict__ batch)
{
    int tid = threadIdx.x;
    if (blockIdx.x == 0) {
        #pragma unroll
        for (int v = 0; v < 32; v++) {
            int idx   = tid + v * 256;
            int r     = idx & 1;
            int lane_ = (idx >> 1) & 31;
            int nt    = (idx >> 6) & 15;
            int kk    = idx >> 10;
            int k = kk * 16 + r * 8 + (lane_ & 3) * 2;
            int n = nt * 8 + (lane_ >> 2);
            size_t o0 = (size_t)k * CH + n;
            size_t o1 = (size_t)(k + 1) * CH + n;
            g_W1p[idx] = h2u(__floats2half2_rn(__ldg(W1 + o0), __ldg(W1 + o1)));
            g_W2p[idx] = h2u(__floats2half2_rn(__ldg(W2 + o0), __ldg(W2 + o1)));
        }
    } else {
        int i = (blockIdx.x - 1) * 256 + tid;
        if (i * 2 + 1 < N_EDGES_C) {
            int2 d = *(const int2*)(dst + i * 2);
            atomicAdd(&g_cnt[d.x], 1);
            atomicAdd(&g_cnt[d.y], 1);
        } else if (i * 2 < N_EDGES_C) {
            atomicAdd(&g_cnt[dst[i * 2]], 1);
        }
        if (i < N_NODES_C) atomicAdd(&g_gcnt[batch[i]], 1.0f);
    }
}

// ---------------- single-pass decoupled-lookback scan + rowptr/cursor/dis + cnt reset ----------------
__global__ __launch_bounds__(256) void scan_lookback_kernel() {
    __shared__ int s[256];
    __shared__ int sP;
    const int b = blockIdx.x;
    const int t = threadIdx.x;
    const int i = b * 256 + t;

    int c = (i < N_NODES_C) ? g_cnt[i] : 0;
    s[t] = c;
    __syncthreads();
    for (int o = 1; o < 256; o <<= 1) {
        int u = (t >= o) ? s[t - o] : 0;
        __syncthreads();
        s[t] += u;
        __syncthreads();
    }
    const int total = s[255];

    if (b == 0) {
        if (t == 0) {
            atomicExch(&g_scan_state[0], (2ull << 32) | (unsigned)total);
            sP = 0;
        }
    } else {
        if (t == 0)
            atomicExch(&g_scan_state[b], (1ull << 32) | (unsigned)total);
        if (t < 32) {
            int lane = t;
            int P = 0;
            int j = b - 1;
            while (true) {
                int idx = j - lane;
                int flag = 0, val = 0;
                if (idx >= 0) {
                    unsigned long long v;
                    do { v = atomicAdd(&g_scan_state[idx], 0ull); flag = (int)(v >> 32); }
                    while (flag == 0);
                    val = (int)(v & 0xffffffffu);
                }
                unsigned m = __ballot_sync(0xFFFFFFFFu, (idx >= 0) && (flag == 2));
                if (m) {
                    int firstP = __ffs(m) - 1;
                    int contrib = (lane <= firstP) ? val : 0;
                    P += __reduce_add_sync(0xFFFFFFFFu, contrib);
                    break;
                } else {
                    P += __reduce_add_sync(0xFFFFFFFFu, (idx >= 0) ? val : 0);
                    j -= 32;
                }
            }
            if (lane == 0) {
                atomicExch(&g_scan_state[b], (2ull << 32) | (unsigned)(P + total));
                sP = P;
            }
        }
    }
    __syncthreads();

    if (i < N_NODES_C) {
        int pos = sP + s[t] - c;
        g_rowptr[i] = pos;
        g_cursor[i] = pos;
        g_dis[i]    = rsqrtf(1.0f + (float)c);
        g_cnt[i]    = 0;
    }
    if (b == 0 && t == 0) g_rowptr[N_NODES_C] = N_EDGES_C;
}

// ---------------- CSR fill (+ scan-state reset) ----------------
__global__ void csr_fill_kernel(const int* __restrict__ src, const int* __restrict__ dst) {
    int i = blockIdx.x * blockDim.x + threadIdx.x;
    if (i < 512) g_scan_state[i] = 0ull;
    if (i * 2 + 1 < N_EDGES_C) {
        int2 s = *(const int2*)(src + i * 2);
        int2 d = *(const int2*)(dst + i * 2);
        g_csr_src[atomicAdd(&g_cursor[d.x], 1)] = s.x;
        g_csr_src[atomicAdd(&g_cursor[d.y], 1)] = s.y;
    } else if (i * 2 < N_EDGES_C) {
        g_csr_src[atomicAdd(&g_cursor[dst[i * 2]], 1)] = src[i * 2];
    }
}

// ---------------- fp16 tensor-core GEMM: Y[r,:] = half((X[r,:] @ W) * scale[r]) ----------------
template <typename T>
__global__ __launch_bounds__(256) void gemm_f16_kernel(
    const T* __restrict__ X, const uint32_t* __restrict__ Wp,
    __half* __restrict__ Y, const float* __restrict__ scale, int M)
{
    __shared__ __half sX[128 * SXP];

    const int tid  = threadIdx.x;
    const int warp = tid >> 5;
    const int lane = tid & 31;
    const int gid  = lane >> 2;
    const int tig  = lane & 3;
    const int rowBase = blockIdx.x * 128;

    if (sizeof(T) == 4) {                    // fp32 input (layer 1)
        const float* Xf = (const float*)X;
        #pragma unroll
        for (int v = 0; v < 16; v++) {
            int fi = tid + v * 256;
            int r  = fi >> 5;
            int c4 = (fi & 31) * 4;
            float4 val = make_float4(0.f, 0.f, 0.f, 0.f);
            int gr = rowBase + r;
            if (gr < M) val = *(const float4*)(Xf + (size_t)gr * CH + c4);
            uint32_t* p = (uint32_t*)(sX + r * SXP + c4);
            p[0] = h2u(__floats2half2_rn(val.x, val.y));
            p[1] = h2u(__floats2half2_rn(val.z, val.w));
        }
    } else {                                 // fp16 input (layer 2)
        const __half* Xh = (const __half*)X;
        #pragma unroll
        for (int v = 0; v < 8; v++) {
            int fi = tid + v * 256;
            int r  = fi >> 4;
            int c8 = (fi & 15) * 8;
            uint4 val = make_uint4(0u, 0u, 0u, 0u);
            int gr = rowBase + r;
            if (gr < M) val = *(const uint4*)(Xh + (size_t)gr * CH + c8);
            uint32_t* p = (uint32_t*)(sX + r * SXP + c8);
            p[0] = val.x; p[1] = val.y; p[2] = val.z; p[3] = val.w;
        }
    }
    __syncthreads();

    float acc[16][4];
    #pragma unroll
    for (int nt = 0; nt < 16; nt++)
        #pragma unroll
        for (int j = 0; j < 4; j++) acc[nt][j] = 0.f;

    const int arow = warp * 16 + gid;

    #pragma unroll
    for (int kk = 0; kk < 8; kk++) {
        uint32_t a0 = *(const uint32_t*)(sX + arow * SXP       + kk * 16 + tig * 2);
        uint32_t a1 = *(const uint32_t*)(sX + (arow + 8) * SXP + kk * 16 + tig * 2);
        uint32_t a2 = *(const uint32_t*)(sX + arow * SXP       + kk * 16 + tig * 2 + 8);
        uint32_t a3 = *(const uint32_t*)(sX + (arow + 8) * SXP + kk * 16 + tig * 2 + 8);
        #pragma unroll
        for (int nt = 0; nt < 16; nt++) {
            uint2 b = *(const uint2*)(Wp + (size_t)(kk * 16 + nt) * 64 + lane * 2);
            float* c = acc[nt];
            asm volatile(
                "mma.sync.aligned.m16n8k16.row.col.f32.f16.f16.f32 "
                "{%0,%1,%2,%3}, {%4,%5,%6,%7}, {%8,%9}, {%0,%1,%2,%3};"
                : "+f"(c[0]), "+f"(c[1]), "+f"(c[2]), "+f"(c[3])
                : "r"(a0), "r"(a1), "r"(a2), "r"(a3), "r"(b.x), "r"(b.y));
        }
    }

    const int r0 = rowBase + warp * 16 + gid;
    const int r1 = r0 + 8;
    const bool v0 = (r0 < M);
    const bool v1 = (r1 < M);
    float s0 = v0 ? scale[r0] : 0.f;
    float s1 = v1 ? scale[r1] : 0.f;
    #pragma unroll
    for (int nt = 0; nt < 16; nt++) {
        int col = nt * 8 + tig * 2;
        if (v0)
            *(__half2*)(Y + (size_t)r0 * CH + col) =
                __floats2half2_rn(acc[nt][0] * s0, acc[nt][1] * s0);
        if (v1)
            *(__half2*)(Y + (size_t)r1 * CH + col) =
                __floats2half2_rn(acc[nt][2] * s1, acc[nt][3] * s1);
    }
}

// ---------------- gather aggregation (fp16 Hs rows pre-scaled by dis[row]) ----------------
// fp16 depth-2 tree accumulation per quad -> one cvt+add per 4 rows.
__device__ __forceinline__ uint2 ld_row(const __half* Hs, int srow, int lane) {
    return *(const uint2*)(Hs + (size_t)srow * CH + lane * 4);
}
__device__ __forceinline__ void add_f4(float4& acc, __half2 c0, __half2 c1) {
    float2 f0 = __half22float2(c0);
    float2 f1 = __half22float2(c1);
    acc.x += f0.x; acc.y += f0.y; acc.z += f1.x; acc.w += f1.y;
}
__device__ __forceinline__ void acc_quad(float4& acc, uint2 r0, uint2 r1, uint2 r2, uint2 r3) {
    __half2 a0 = __hadd2(u2h(r0.x), u2h(r1.x));
    __half2 a1 = __hadd2(u2h(r0.y), u2h(r1.y));
    __half2 b0 = __hadd2(u2h(r2.x), u2h(r3.x));
    __half2 b1 = __hadd2(u2h(r2.y), u2h(r3.y));
    add_f4(acc, __hadd2(a0, b0), __hadd2(a1, b1));
}

template <int MODE>
__global__ __launch_bounds__(256) void agg_kernel(
    const __half* __restrict__ Hs, const float* __restrict__ bias,
    __half* __restrict__ OUT,
    const float* __restrict__ Wfc, const int* __restrict__ batch)
{
    int node = (blockIdx.x * blockDim.x + threadIdx.x) >> 5;
    int lane = threadIdx.x & 31;
    if (node >= N_NODES_C) return;

    float4 acc = make_float4(0.f, 0.f, 0.f, 0.f);
    {   // self term
        uint2 r = ld_row(Hs, node, lane);
        add_f4(acc, u2h(r.x), u2h(r.y));
    }

    int beg = __ldg(&g_rowptr[node]);
    int end = __ldg(&g_rowptr[node + 1]);

    for (int j = beg; j < end; j += 32) {
        int n = min(32, end - j);
        int si = (lane < n) ? __ldg(&g_csr_src[j + lane]) : 0;
        int t = 0;
        for (; t + 8 <= n; t += 8) {         // 8 loads in flight, two fp16 quads
            int ss[8];
            #pragma unroll
            for (int k = 0; k < 8; k++) ss[k] = __shfl_sync(0xFFFFFFFFu, si, t + k);
            uint2 r0 = ld_row(Hs, ss[0], lane);
            uint2 r1 = ld_row(Hs, ss[1], lane);
            uint2 r2 = ld_row(Hs, ss[2], lane);
            uint2 r3 = ld_row(Hs, ss[3], lane);
            uint2 r4 = ld_row(Hs, ss[4], lane);
            uint2 r5 = ld_row(Hs, ss[5], lane);
            uint2 r6 = ld_row(Hs, ss[6], lane);
            uint2 r7 = ld_row(Hs, ss[7], lane);
            acc_quad(acc, r0, r1, r2, r3);
            acc_quad(acc, r4, r5, r6, r7);
        }
        if (t + 4 <= n) {
            int s0 = __shfl_sync(0xFFFFFFFFu, si, t);
            int s1 = __shfl_sync(0xFFFFFFFFu, si, t + 1);
            int s2 = __shfl_sync(0xFFFFFFFFu, si, t + 2);
            int s3 = __shfl_sync(0xFFFFFFFFu, si, t + 3);
            acc_quad(acc, ld_row(Hs, s0, lane), ld_row(Hs, s1, lane),
                          ld_row(Hs, s2, lane), ld_row(Hs, s3, lane));
            t += 4;
        }
        if (t + 2 <= n) {
            int s0 = __shfl_sync(0xFFFFFFFFu, si, t);
            int s1 = __shfl_sync(0xFFFFFFFFu, si, t + 1);
            uint2 r0 = ld_row(Hs, s0, lane);
            uint2 r1 = ld_row(Hs, s1, lane);
            add_f4(acc, __hadd2(u2h(r0.x), u2h(r1.x)), __hadd2(u2h(r0.y), u2h(r1.y)));
            t += 2;
        }
        if (t < n) {
            int s0 = __shfl_sync(0xFFFFFFFFu, si, t);
            uint2 r = ld_row(Hs, s0, lane);
            add_f4(acc, u2h(r.x), u2h(r.y));
        }
    }

    float dd = __ldg(&g_dis[node]);
    float4 b4 = *(const float4*)(bias + lane * 4);
    acc.x = fmaxf(acc.x * dd + b4.x, 0.f);
    acc.y = fmaxf(acc.y * dd + b4.y, 0.f);
    acc.z = fmaxf(acc.z * dd + b4.z, 0.f);
    acc.w = fmaxf(acc.w * dd + b4.w, 0.f);

    if (MODE == 0) {
        uint2 o;
        o.x = h2u(__floats2half2_rn(acc.x, acc.y));
        o.y = h2u(__floats2half2_rn(acc.z, acc.w));
        *(uint2*)(OUT + (size_t)node * CH + lane * 4) = o;
    } else {
        float4 w4 = *(const float4*)(Wfc + lane * 4);
        float s = acc.x * w4.x + acc.y * w4.y + acc.z * w4.z + acc.w * w4.w;
        #pragma unroll
        for (int o = 16; o; o >>= 1) s += __shfl_xor_sync(0xFFFFFFFFu, s, o);
        if (lane == 0) atomicAdd(&g_gsum[__ldg(batch + node)], s);
    }
}

// ---------------- final output (+ pool-state reset) ----------------
__global__ void final_out_kernel(float* __restrict__ out, const float* __restrict__ bfc) {
    int g = threadIdx.x;
    if (g < N_GRAPHS_C) {
        out[g] = g_gsum[g] / fmaxf(g_gcnt[g], 1.0f) + bfc[0];
        g_gsum[g] = 0.f;
        g_gcnt[g] = 0.f;
    }
}

// ---------------- launch (8 kernels, plain launches only) ----------------
extern "C" void kernel_launch(void* const* d_in, const int* in_sizes, int n_in,
                              void* d_out, int out_size)
{
    const float* x    = (const float*)d_in[0];
    const int*   edge = (const int*)  d_in[1];
    const int*   batch= (const int*)  d_in[2];
    const float* W1   = (const float*)d_in[3];
    const float* b1   = (const float*)d_in[4];
    const float* W2   = (const float*)d_in[5];
    const float* b2   = (const float*)d_in[6];
    const float* Wfc  = (const float*)d_in[7];
    const float* bfc  = (const float*)d_in[8];
    float* out = (float*)d_out;

    const int* srcp = edge;
    const int* dstp = edge + N_EDGES_C;

    __half *bufA = nullptr, *bufB = nullptr;
    float *disp = nullptr;
    uint32_t *w1p = nullptr, *w2p = nullptr;
    cudaGetSymbolAddress((void**)&bufA, g_bufA);
    cudaGetSymbolAddress((void**)&bufB, g_bufB);
    cudaGetSymbolAddress((void**)&disp, g_dis);
    cudaGetSymbolAddress((void**)&w1p, g_W1p);
    cudaGetSymbolAddress((void**)&w2p, g_W2p);

    const int agrid = (N_NODES_C + 7) / 8;

    // ---- fused prepack + degree/graph count ----
    prepack_cnt_kernel<<<E2GRID + 1, 256>>>(W1, W2, dstp, batch);

    // ---- scan: rowptr/cursor/dis ----
    scan_lookback_kernel<<<NBLK, 256>>>();

    // ---- CSR fill ----
    csr_fill_kernel<<<E2GRID, 256>>>(srcp, dstp);

    // ---- layer 1 ----
    gemm_f16_kernel<float><<<GGRID, 256>>>(x, w1p, bufA, disp, N_NODES_C);
    agg_kernel<0><<<agrid, 256>>>(bufA, b1, bufB, nullptr, nullptr);

    // ---- layer 2 ----
    gemm_f16_kernel<__half><<<GGRID, 256>>>(bufB, w2p, bufA, disp, N_NODES_C);
    agg_kernel<1><<<agrid, 256>>>(bufA, b2, nullptr, Wfc, batch);

    // ---- final (+ reset pooling state) ----
    final_out_kernel<<<1, 256>>>(out, bfc);

    (void)in_sizes; (void)n_in; (void)out_size;
}